// round 4
// baseline (speedup 1.0000x reference)
#include <cuda_runtime.h>
#include <cstdint>

// EdgeFeature: B=4, D=64, N=4096, K=16
// out = [ edge_feature (4,128,4096,16) fp32 ; idx (4,65536) as fp32 ]

#define B_ 4
#define D_ 64
#define N_ 4096
#define K_ 16

// Scratch (static __device__ — no allocations allowed in kernel_launch)
__device__ float g_sq[B_ * N_];                       // 64 KB
__device__ float g_dist[(size_t)B_ * N_ * N_];        // 256 MB (fp32 dist, post-sqrt)
__device__ int   g_idx[B_ * N_ * K_];                 // 1 MB

// ---------------------------------------------------------------------------
// 1) squared norms (sequential ascending d, fmaf — matches the GEMM's dot
//    accumulation order so self-distance cancels to exactly 0.0f)
// ---------------------------------------------------------------------------
__global__ void sq_kernel(const float* __restrict__ pc) {
    int gid = blockIdx.x * blockDim.x + threadIdx.x;
    int b = gid >> 12;
    int n = gid & (N_ - 1);
    const float* X = pc + (size_t)b * D_ * N_;
    float acc = 0.0f;
    #pragma unroll
    for (int d = 0; d < D_; d++) {
        float v = X[d * N_ + n];
        acc = fmaf(v, v, acc);
    }
    g_sq[gid] = acc;
}

// ---------------------------------------------------------------------------
// 2) dist[b][i][j] = sqrt(max(sq_i + sq_j - 2*dot(x_i, x_j), 0))
//    Round-2 proven version: full grid, 128x128 CTA tile, 256 threads,
//    8x8 micro-tile, scalar FFMA, coalesced float4 stores only.
// ---------------------------------------------------------------------------
__global__ __launch_bounds__(256, 2) void d2_kernel(const float* __restrict__ pc) {
    __shared__ float As[32][128];
    __shared__ float Bs[32][128];
    __shared__ float sqa[128];
    __shared__ float sqb[128];

    int b  = blockIdx.z;
    int i0 = blockIdx.y * 128;
    int j0 = blockIdx.x * 128;
    const float* X = pc + (size_t)b * D_ * N_;
    int t = threadIdx.x;

    if (t < 128) sqa[t]       = g_sq[b * N_ + i0 + t];
    else         sqb[t - 128] = g_sq[b * N_ + j0 + (t - 128)];

    int r = t >> 4;    // 0..15 (row group)
    int c = t & 15;    // 0..15 (col group)

    float acc[8][8];
    #pragma unroll
    for (int ii = 0; ii < 8; ii++)
        #pragma unroll
        for (int jj = 0; jj < 8; jj++)
            acc[ii][jj] = 0.0f;

    for (int dc = 0; dc < D_; dc += 32) {
        __syncthreads();
        for (int l = t; l < 1024; l += 256) {
            int d  = l >> 5;
            int i4 = (l & 31) << 2;
            *(float4*)&As[d][i4] = *(const float4*)&X[(size_t)(dc + d) * N_ + i0 + i4];
            *(float4*)&Bs[d][i4] = *(const float4*)&X[(size_t)(dc + d) * N_ + j0 + i4];
        }
        __syncthreads();

        #pragma unroll 8
        for (int d = 0; d < 32; d++) {
            float a[8], bb[8];
            *(float4*)&a[0]  = *(float4*)&As[d][r * 8];
            *(float4*)&a[4]  = *(float4*)&As[d][r * 8 + 4];
            *(float4*)&bb[0] = *(float4*)&Bs[d][c * 8];
            *(float4*)&bb[4] = *(float4*)&Bs[d][c * 8 + 4];
            #pragma unroll
            for (int ii = 0; ii < 8; ii++)
                #pragma unroll
                for (int jj = 0; jj < 8; jj++)
                    acc[ii][jj] = fmaf(a[ii], bb[jj], acc[ii][jj]);
        }
    }

    // epilogue: dist = sqrt(clamp(sq_i + sq_j - 2*dot, 0)); 2*acc exact so
    // rounding matches the reference regardless of FMA contraction.
    #pragma unroll
    for (int ii = 0; ii < 8; ii++) {
        int   row = i0 + r * 8 + ii;
        float si  = sqa[r * 8 + ii];
        float* dst = g_dist + ((size_t)(b * N_ + row) << 12) + j0 + c * 8;
        float v[8];
        #pragma unroll
        for (int jj = 0; jj < 8; jj++) {
            float s = si + sqb[c * 8 + jj];
            v[jj] = sqrtf(fmaxf(s - 2.0f * acc[ii][jj], 0.0f));
        }
        *(float4*)&dst[0] = *(float4*)&v[0];
        *(float4*)&dst[4] = *(float4*)&v[4];
    }
}

// ---------------------------------------------------------------------------
// 3) per-row top-(K+1) via histogram threshold + tiny exact selection.
//    Bucket = dist_bits >> 21 (monotone for nonneg floats). Find the bucket
//    containing the 17th smallest, compact all candidates with bucket <= B
//    (typically ~25, worst case 4096), then one warp runs exact 17-pass
//    argmin on u64 keys (dist_bits<<32)|j -> identical order to lax.top_k.
// ---------------------------------------------------------------------------
__global__ __launch_bounds__(256) void select_kernel(float* __restrict__ out_idx_f) {
    __shared__ int hist[2048];
    __shared__ unsigned long long buf[4096];
    __shared__ int wsum[8];
    __shared__ int Bsh;
    __shared__ int cnt;

    int row = blockIdx.x;                      // b*4096 + i
    const float* src = g_dist + (size_t)row * N_;
    int t = threadIdx.x;
    int lane = t & 31, w = t >> 5;

    #pragma unroll
    for (int q = 0; q < 8; q++) hist[t + 256 * q] = 0;
    if (t == 0) cnt = 0;
    __syncthreads();

    unsigned bits[16];
    #pragma unroll
    for (int jj = 0; jj < 16; jj++) {
        bits[jj] = __float_as_uint(src[t + jj * 256]);
        atomicAdd(&hist[bits[jj] >> 21], 1);
    }
    __syncthreads();

    // scan over 2048 buckets: thread t owns buckets [t*8, t*8+8)
    int h[8], s = 0;
    #pragma unroll
    for (int q = 0; q < 8; q++) { h[q] = hist[t * 8 + q]; s += h[q]; }
    int x = s;
    #pragma unroll
    for (int off = 1; off < 32; off <<= 1) {
        int y = __shfl_up_sync(0xffffffffu, x, off);
        if (lane >= off) x += y;
    }
    if (lane == 31) wsum[w] = x;
    __syncthreads();
    int wo = 0;
    #pragma unroll
    for (int q = 0; q < 8; q++) wo += (q < w) ? wsum[q] : 0;
    int cum = wo + x - s;                      // exclusive prefix at chunk start
    #pragma unroll
    for (int q = 0; q < 8; q++) {
        if (cum < (K_ + 1) && cum + h[q] >= (K_ + 1)) Bsh = t * 8 + q;
        cum += h[q];
    }
    __syncthreads();

    int Bv = Bsh;
    #pragma unroll
    for (int jj = 0; jj < 16; jj++) {
        if ((int)(bits[jj] >> 21) <= Bv) {
            int p = atomicAdd(&cnt, 1);
            buf[p] = ((unsigned long long)bits[jj] << 32) | (unsigned)(t + jj * 256);
        }
    }
    __syncthreads();

    if (w == 0) {
        int n = cnt;
        for (int p = 0; p <= K_; p++) {
            unsigned long long m = 0xFFFFFFFFFFFFFFFFull;
            for (int i = lane; i < n; i += 32) m = (buf[i] < m) ? buf[i] : m;
            #pragma unroll
            for (int off = 16; off; off >>= 1) {
                unsigned long long o = __shfl_xor_sync(0xffffffffu, m, off);
                m = (o < m) ? o : m;
            }
            for (int i = lane; i < n; i += 32)
                if (buf[i] == m) buf[i] = 0xFFFFFFFFFFFFFFFFull;
            if (lane == 0 && p > 0) {
                int j = (int)(m & 0xFFFFFFFFu);
                g_idx[row * K_ + (p - 1)]     = j;
                out_idx_f[row * K_ + (p - 1)] = (float)j;
            }
        }
    }
}

// ---------------------------------------------------------------------------
// 4) gather + concat epilogue. 4-way channel split -> 2048 blocks (~14/SM)
//    to fix the parallelism starvation seen in ncu (occ 34.5%, issue 10%).
//    Per block: 16 channels x (32 n x 16 k); (n,k) slab contiguous -> 1 KB
//    coalesced stores; gathers hit L2 (point cloud is 4 MB).
// ---------------------------------------------------------------------------
__global__ __launch_bounds__(256) void gather_kernel(const float* __restrict__ pc,
                                                     float* __restrict__ out) {
    __shared__ int   sidx[32 * K_];
    __shared__ float cen[16][32];

    int blk = blockIdx.x;             // 2048 blocks: b | ntile | cq
    int cq  = blk & 3;                // channel quarter (16 channels)
    int nt  = (blk >> 2) & 127;
    int b   = blk >> 9;
    int n0  = nt * 32;
    int c0  = cq * 16;
    int t   = threadIdx.x;
    const float* pcb = pc + (size_t)b * D_ * N_;

    for (int l = t; l < 32 * K_; l += 256)
        sidx[l] = g_idx[(b * N_ + n0) * K_ + l];
    for (int l = t; l < 16 * 32; l += 256) {
        int d = l >> 5, n = l & 31;
        cen[d][n] = pcb[(c0 + d) * N_ + n0 + n];
    }
    __syncthreads();

    size_t obase = (size_t)b * 2 * D_ * N_ * K_;
    #pragma unroll 4
    for (int cc = 0; cc < 16; cc++) {
        int c = c0 + cc;
        #pragma unroll
        for (int q = 0; q < 2; q++) {
            int l = t + q * 256;          // 512 (n,k) pairs
            int n = l >> 4, k = l & 15;
            float ce = cen[cc][n];
            float nb = __ldg(&pcb[c * N_ + sidx[l]]);
            size_t o = obase + ((size_t)c * N_ + n0 + n) * K_ + k;
            out[o]                        = ce;        // central channels 0..63
            out[o + (size_t)D_ * N_ * K_] = nb - ce;   // neighbor-central 64..127
        }
    }
}

// ---------------------------------------------------------------------------
extern "C" void kernel_launch(void* const* d_in, const int* in_sizes, int n_in,
                              void* d_out, int out_size) {
    const float* pc = (const float*)d_in[0];
    float* out = (float*)d_out;
    float* out_idx = out + (size_t)B_ * 2 * D_ * N_ * K_;

    sq_kernel<<<(B_ * N_) / 256, 256>>>(pc);
    dim3 gg(N_ / 128, N_ / 128, B_);
    d2_kernel<<<gg, 256>>>(pc);
    select_kernel<<<B_ * N_, 256>>>(out_idx);
    gather_kernel<<<B_ * 128 * 4, 256>>>(pc, out);
}